// round 16
// baseline (speedup 1.0000x reference)
#include <cuda_runtime.h>
#include <cuda_fp16.h>
#include <math.h>

#define EPSF 1e-5f
#define PI_OVER_32 0.09817477042468103f

// ---------------- constant permutations ----------------
__constant__ int c_IDX[16]  = {0,7,10,13,1,4,11,14,2,5,8,15,3,6,9,12};
__constant__ int c_BACK[16] = {0,4,8,12,5,9,13,1,10,14,2,6,15,3,7,11};

// ---------------- device scratch (no allocs allowed) ----------------
__device__ float  g_u  [16*16*256*256];
__device__ float  g_y  [16*16*256*256];
__device__ float  g_acc[16*4*256*256];
__device__ float  g_t  [16*4*256*256];
__device__ __half g_ln [16*4*256*256];
__device__ float  g_qkv[16*4*256*128];    // ld=128 (cols 96..127 pad)
__device__ __half g_att[16*4*256*32];
__device__ __half g_mlp[16*4*256*512];
__device__ float  g_zp [16*64*64*256];
__device__ float2 g_f1 [16*64*33*256];
__device__ float2 g_f2 [16*64*33*256];
__device__ __half g_zf [16*256*64*64];    // fp16 (conv3 B-side)
__device__ __half g_c3 [16*256*64*64];    // fp16 (conv4 B-side)
// fp16 weight / input copies (converted once per launch)
__device__ __half g_xh   [16*256*4096];
__device__ __half g_wqkvh[2*256*96];
__device__ __half g_wouth[2*32*256];
__device__ __half g_w1h  [2*256*512];
__device__ __half g_w2h  [2*512*256];
__device__ __half g_c3wh [256*512];
__device__ __half g_c4wh [256*2304];

// fp16 m16n8k16 mma, fp32 accumulate
__device__ __forceinline__ void mma16(float* d, const unsigned* a, unsigned b0, unsigned b1) {
    asm volatile(
        "mma.sync.aligned.m16n8k16.row.col.f32.f16.f16.f32 "
        "{%0,%1,%2,%3}, {%4,%5,%6,%7}, {%8,%9}, {%0,%1,%2,%3};"
        : "+f"(d[0]), "+f"(d[1]), "+f"(d[2]), "+f"(d[3])
        : "r"(a[0]), "r"(a[1]), "r"(a[2]), "r"(a[3]), "r"(b0), "r"(b1));
}

// ---------------- f32 -> f16 conversion (vectorized) ----------------
__global__ void f2h_kernel(const float4* __restrict__ in, uint2* __restrict__ out, int n4) {
    int i = blockIdx.x * 256 + threadIdx.x;
    if (i < n4) {
        float4 v = in[i];
        __half2 lo = __floats2half2_rn(v.x, v.y);
        __half2 hi = __floats2half2_rn(v.z, v.w);
        uint2 st; st.x = *(unsigned*)&lo; st.y = *(unsigned*)&hi;
        out[i] = st;
    }
}

// ---------------- tiny utility kernels ----------------
__global__ void unfold_kernel(const float* __restrict__ x, float* __restrict__ u) {
    __shared__ float tile[32][33];
    int b  = blockIdx.z;
    int c0 = blockIdx.y * 32;
    int s0 = blockIdx.x * 32;
    int tx = threadIdx.x & 31, ty = threadIdx.x >> 5;
    #pragma unroll
    for (int cc = 0; cc < 4; cc++)
        tile[ty + cc * 8][tx] =
            x[(size_t)(b * 256 + c0 + ty + cc * 8) * 4096 + s0 + tx];
    __syncthreads();
    #pragma unroll
    for (int cc = 0; cc < 4; cc++) {
        int s = s0 + ty + cc * 8;
        int h = s >> 6, w = s & 63;
        int kp = (h & 3) * 4 + (w & 3);
        int j = c_BACK[kp];
        int l = (h >> 2) * 16 + (w >> 2);
        u[((size_t)(b * 16 + j) * 256 + l) * 256 + c0 + tx] = tile[tx][ty + cc * 8];
    }
}

__device__ __forceinline__ float4 f4add(float4 a, float4 b) {
    return make_float4(a.x + b.x, a.y + b.y, a.z + b.z, a.w + b.w);
}

__global__ void t_init_kernel(const float4* __restrict__ u, float4* __restrict__ t) {
    int i = blockIdx.x * 256 + threadIdx.x;
    int c4 = i & 63;
    int l = (i >> 6) & 255;
    int p = (i >> 14) & 3;
    int b = i >> 16;
    t[i] = u[((size_t)(b * 16 + p) * 256 + l) * 64 + c4];
}

__global__ void group_step_kernel(const float4* __restrict__ u, float4* __restrict__ t,
                                  float4* __restrict__ y, float4* __restrict__ acc,
                                  int g, int first) {
    int i = blockIdx.x * 256 + threadIdx.x;
    int c4 = i & 63;
    int l = (i >> 6) & 255;
    int p = (i >> 14) & 3;
    int b = i >> 16;
    float4 v = t[i];
    y[((size_t)(b * 16 + g * 4 + p) * 256 + l) * 64 + c4] = v;
    float4 a = first ? v : f4add(acc[i], v);
    acc[i] = a;
    t[i] = f4add(u[((size_t)(b * 16 + (g + 1) * 4 + p) * 256 + l) * 64 + c4], a);
}

__global__ void y_store_kernel(const float4* __restrict__ t, float4* __restrict__ y, int g) {
    int i = blockIdx.x * 256 + threadIdx.x;
    int c4 = i & 63;
    int l = (i >> 6) & 255;
    int p = (i >> 14) & 3;
    int b = i >> 16;
    y[((size_t)(b * 16 + g * 4 + p) * 256 + l) * 64 + c4] = t[i];
}

__global__ void fold_kernel(const float4* __restrict__ y, float4* __restrict__ zp) {
    int i = blockIdx.x * 256 + threadIdx.x;
    int c4 = i & 63;
    int wp = (i >> 6) & 63;
    int hp = (i >> 12) & 63;
    int b  = i >> 18;
    int ky = hp & 3, ph = hp >> 2;
    int kx = wp & 3, pw = wp >> 2;
    int j = c_BACK[ky * 4 + kx];
    int l = ph * 16 + pw;
    zp[i] = y[((size_t)(b * 16 + j) * 256 + l) * 64 + c4];
}

// ---------------- layernorm: 4 rows per block, float4 in, fp16 out ----------------
__global__ void ln_kernel(const float* __restrict__ in, const float* __restrict__ gw,
                          const float* __restrict__ bw, __half* __restrict__ out) {
    int tid = threadIdx.x;
    int r = tid >> 6;
    int t = tid & 63;
    size_t row = (size_t)blockIdx.x * 4 + r;
    float4 v = *(const float4*)(in + row * 256 + t * 4);
    float s  = v.x + v.y + v.z + v.w;
    float sq = v.x * v.x + v.y * v.y + v.z * v.z + v.w * v.w;
    #pragma unroll
    for (int o = 16; o; o >>= 1) {
        s  += __shfl_xor_sync(0xffffffffu, s, o);
        sq += __shfl_xor_sync(0xffffffffu, sq, o);
    }
    __shared__ float ss[8], sqs[8];
    int warp = tid >> 5;
    if ((tid & 31) == 0) { ss[warp] = s; sqs[warp] = sq; }
    __syncthreads();
    s  = ss[r * 2] + ss[r * 2 + 1];
    sq = sqs[r * 2] + sqs[r * 2 + 1];
    float mean = s * (1.f / 256.f);
    float var  = sq * (1.f / 256.f) - mean * mean;
    float rstd = rsqrtf(var + EPSF);
    float4 g4 = *(const float4*)(gw + t * 4);
    float4 b4 = *(const float4*)(bw + t * 4);
    __half2 lo = __floats2half2_rn((v.x - mean) * rstd * g4.x + b4.x,
                                   (v.y - mean) * rstd * g4.y + b4.y);
    __half2 hi = __floats2half2_rn((v.z - mean) * rstd * g4.z + b4.z,
                                   (v.w - mean) * rstd * g4.w + b4.w);
    uint2 st; st.x = *(unsigned*)&lo; st.y = *(unsigned*)&hi;
    *(uint2*)(out + row * 256 + t * 4) = st;
}

// ============ all-fp16-operand mma GEMM: BM=128, BN=128, BK=16, 8 warps ======
// A fp16 direct; B fp16 (dual source, ksplit); template<OH>: C fp16/fp32.
#define BM 128
#define BNN 128
#define BK 16
#define ALD2 10
#define BLD2 136

template<int OH>
__global__ void __launch_bounds__(256)
gemm_kernel_t(const __half* __restrict__ Ah, const __half* __restrict__ B,
              const __half* __restrict__ B2, int ksplit,
              void* __restrict__ Cv,
              const float* __restrict__ bias, const float* __restrict__ resid,
              const float* __restrict__ bnG, const float* __restrict__ bnB,
              const float* __restrict__ bnM, const float* __restrict__ bnV,
              int M, int N, int K, int lda, int ldb, int ldc,
              int act, long long sA, long long sB, long long sC) {
    __shared__ __align__(16) __half2 As2[2][BM][ALD2];
    __shared__ __align__(16) __half2 Bs2[2][8][BLD2];
    int z = blockIdx.z;
    Ah += (size_t)z * sA;
    B += (size_t)z * sB; if (B2) B2 += (size_t)z * sB;
    float*  Cf = (float*)Cv  + (OH ? 0 : (size_t)z * sC);
    __half* Ch = (__half*)Cv + (OH ? (size_t)z * sC : 0);
    const float* R = resid ? resid + (size_t)z * sC : (const float*)0;
    int bm = blockIdx.y * BM, bn = blockIdx.x * BNN;
    int tid = threadIdx.x, warp = tid >> 5, lane = tid & 31;
    int wr = warp >> 1, wc = warp & 1;
    int lg = lane >> 2, lq = lane & 3;

    float acc[2][8][4];
    #pragma unroll
    for (int r = 0; r < 2; r++)
        #pragma unroll
        for (int c = 0; c < 8; c++)
            #pragma unroll
            for (int e = 0; e < 4; e++)
                acc[r][c][e] = 0.f;

    int aRowH = tid >> 1, akh = (tid & 1) * 8;
    int sb = akh >> 3;
    int bRow = tid >> 5;
    int bN = (tid & 31) * 4;
    int cB = bn + bN;
    bool bOK = (cB < N);

    uint4 pah;
    uint2 pbh[2];
    const uint2 u2z = make_uint2(0u, 0u);

    // ---- initial loads (k0 = 0) ----
    pah = *(const uint4*)(Ah + (size_t)(bm + aRowH) * lda + akh);
    #pragma unroll
    for (int j = 0; j < 2; j++) {
        int k = 2 * bRow + j;
        const __half* q = (k < ksplit) ? B + (size_t)k * ldb
                                       : B2 + (size_t)(k - ksplit) * ldb;
        pbh[j] = bOK ? *(const uint2*)(q + cB) : u2z;
    }
    {
        const __half2* hp = (const __half2*)&pah;
        #pragma unroll
        for (int p = 0; p < 4; p++)
            As2[0][aRowH][sb + 2 * p] = hp[p];
        const __half* r0 = (const __half*)&pbh[0];
        const __half* r1 = (const __half*)&pbh[1];
        __half2 h[4];
        #pragma unroll
        for (int e = 0; e < 4; e++)
            h[e] = __halves2half2(r0[e], r1[e]);
        *(uint4*)&Bs2[0][bRow][bN] = *(uint4*)h;
    }
    __syncthreads();

    int cur = 0;
    for (int k0 = 0; k0 < K; k0 += BK) {
        int kn = k0 + BK;
        if (kn < K) {
            pah = *(const uint4*)(Ah + (size_t)(bm + aRowH) * lda + kn + akh);
            #pragma unroll
            for (int j = 0; j < 2; j++) {
                int k = kn + 2 * bRow + j;
                const __half* q = (k < ksplit) ? B + (size_t)k * ldb
                                               : B2 + (size_t)(k - ksplit) * ldb;
                pbh[j] = bOK ? *(const uint2*)(q + cB) : u2z;
            }
        }
        {
            unsigned a[2][4];
            #pragma unroll
            for (int r = 0; r < 2; r++) {
                int row = wr * 32 + r * 16 + lg;
                uint2 lo = *(const uint2*)&As2[cur][row][2 * lq];
                uint2 hi = *(const uint2*)&As2[cur][row + 8][2 * lq];
                a[r][0] = lo.x; a[r][1] = hi.x; a[r][2] = lo.y; a[r][3] = hi.y;
            }
            #pragma unroll
            for (int c = 0; c < 8; c++) {
                int nn = wc * 64 + c * 8 + lg;
                unsigned b0 = *(const unsigned*)&Bs2[cur][lq][nn];
                unsigned b1 = *(const unsigned*)&Bs2[cur][lq + 4][nn];
                #pragma unroll
                for (int r = 0; r < 2; r++)
                    mma16(acc[r][c], a[r], b0, b1);
            }
        }
        if (kn < K) {
            const __half2* hp = (const __half2*)&pah;
            #pragma unroll
            for (int p = 0; p < 4; p++)
                As2[cur ^ 1][aRowH][sb + 2 * p] = hp[p];
            const __half* r0 = (const __half*)&pbh[0];
            const __half* r1 = (const __half*)&pbh[1];
            __half2 h[4];
            #pragma unroll
            for (int e = 0; e < 4; e++)
                h[e] = __halves2half2(r0[e], r1[e]);
            *(uint4*)&Bs2[cur ^ 1][bRow][bN] = *(uint4*)h;
        }
        __syncthreads();
        cur ^= 1;
    }

    // direct epilogue: resid -> bias -> bn-affine(row) -> silu
    #pragma unroll
    for (int r = 0; r < 2; r++) {
        #pragma unroll
        for (int half = 0; half < 2; half++) {
            int row = bm + wr * 32 + r * 16 + lg + half * 8;
            float sc = 1.f, sh = 0.f;
            if (bnG) {
                float s_ = bnG[row] * rsqrtf(bnV[row] + EPSF);
                sc = s_; sh = bnB[row] - bnM[row] * s_;
            }
            #pragma unroll
            for (int c = 0; c < 8; c++) {
                int col = bn + wc * 64 + c * 8 + 2 * lq;
                if (col < N) {
                    float v0 = acc[r][c][half * 2];
                    float v1 = acc[r][c][half * 2 + 1];
                    if (R) {
                        float2 rv = *(const float2*)(R + (size_t)row * ldc + col);
                        v0 += rv.x; v1 += rv.y;
                    }
                    if (bias) {
                        float2 bv = *(const float2*)(bias + col);
                        v0 += bv.x; v1 += bv.y;
                    }
                    v0 = v0 * sc + sh;
                    v1 = v1 * sc + sh;
                    if (act) {
                        v0 = v0 / (1.f + __expf(-v0));
                        v1 = v1 / (1.f + __expf(-v1));
                    }
                    if (OH) {
                        __half2 hv = __floats2half2_rn(v0, v1);
                        *(__half2*)(Ch + (size_t)row * ldc + col) = hv;
                    } else {
                        *(float2*)(Cf + (size_t)row * ldc + col) = make_float2(v0, v1);
                    }
                }
            }
        }
    }
}

// ---------------- conv4 implicit GEMM: fp16 weights + fp16 image ----------------
__global__ void __launch_bounds__(256)
conv4_gemm_kernel(const __half* __restrict__ W, const __half* __restrict__ img,
                  float* __restrict__ C,
                  const float* __restrict__ bnG, const float* __restrict__ bnB,
                  const float* __restrict__ bnM, const float* __restrict__ bnV) {
    __shared__ __align__(16) __half2 As2[2][BM][ALD2];
    __shared__ __align__(16) __half2 Bs2[2][8][BLD2];
    const int K = 2304;
    int z = blockIdx.z;
    img += (size_t)z * 256 * 4096;
    C   += (size_t)z * 256 * 4096;
    int bm = blockIdx.y * BM, bn = blockIdx.x * BNN;
    int tid = threadIdx.x, warp = tid >> 5, lane = tid & 31;
    int wr = warp >> 1, wc = warp & 1;
    int lg = lane >> 2, lq = lane & 3;
    const __half hz = __float2half(0.f);

    float acc[2][8][4];
    #pragma unroll
    for (int r = 0; r < 2; r++)
        #pragma unroll
        for (int c = 0; c < 8; c++)
            #pragma unroll
            for (int e = 0; e < 4; e++)
                acc[r][c][e] = 0.f;

    int aRowH = tid >> 1, akh = (tid & 1) * 8;
    int sb = akh >> 3;
    int bRow = tid >> 5;
    int bN = (tid & 31) * 4;
    int n = bn + bN;
    int y0 = n >> 6, x0 = n & 63;

    uint4 pah;
    __half pbv[2][4];

    auto loadB = [&](int kbase) {
        #pragma unroll
        for (int j = 0; j < 2; j++) {
            int k = kbase + 2 * bRow + j;
            int ic = k / 9, kk = k - ic * 9;
            int ky = kk / 3, kx = kk - ky * 3;
            int gy = y0 + ky - 1;
            const __half* p = img + ((size_t)ic * 64 + gy) * 64;
            bool rok = (unsigned)gy < 64u;
            #pragma unroll
            for (int e = 0; e < 4; e++) {
                int gx = x0 + e + kx - 1;
                pbv[j][e] = (rok && (unsigned)gx < 64u) ? p[gx] : hz;
            }
        }
    };
    auto storeB = [&](int st) {
        __half2 h[4];
        #pragma unroll
        for (int e = 0; e < 4; e++)
            h[e] = __halves2half2(pbv[0][e], pbv[1][e]);
        *(uint4*)&Bs2[st][bRow][bN] = *(uint4*)h;
    };
    auto storeA = [&](int st) {
        const __half2* hp = (const __half2*)&pah;
        #pragma unroll
        for (int p = 0; p < 4; p++)
            As2[st][aRowH][sb + 2 * p] = hp[p];
    };

    pah = *(const uint4*)(W + (size_t)(bm + aRowH) * 2304 + akh);
    loadB(0);
    storeA(0);
    storeB(0);
    __syncthreads();

    int cur = 0;
    for (int k0 = 0; k0 < K; k0 += BK) {
        int kn = k0 + BK;
        if (kn < K) {
            pah = *(const uint4*)(W + (size_t)(bm + aRowH) * 2304 + kn + akh);
            loadB(kn);
        }
        {
            unsigned a[2][4];
            #pragma unroll
            for (int r = 0; r < 2; r++) {
                int row = wr * 32 + r * 16 + lg;
                uint2 lo = *(const uint2*)&As2[cur][row][2 * lq];
                uint2 hi = *(const uint2*)&As2[cur][row + 8][2 * lq];
                a[r][0] = lo.x; a[r][1] = hi.x; a[r][2] = lo.y; a[r][3] = hi.y;
            }
            #pragma unroll
            for (int c = 0; c < 8; c++) {
                int nn = wc * 64 + c * 8 + lg;
                unsigned b0 = *(const unsigned*)&Bs2[cur][lq][nn];
                unsigned b1 = *(const unsigned*)&Bs2[cur][lq + 4][nn];
                #pragma unroll
                for (int r = 0; r < 2; r++)
                    mma16(acc[r][c], a[r], b0, b1);
            }
        }
        if (kn < K) {
            storeA(cur ^ 1);
            storeB(cur ^ 1);
        }
        __syncthreads();
        cur ^= 1;
    }

    #pragma unroll
    for (int r = 0; r < 2; r++) {
        #pragma unroll
        for (int half = 0; half < 2; half++) {
            int row = bm + wr * 32 + r * 16 + lg + half * 8;
            float s_ = bnG[row] * rsqrtf(bnV[row] + EPSF);
            float sh = bnB[row] - bnM[row] * s_;
            #pragma unroll
            for (int c = 0; c < 8; c++) {
                int col = bn + wc * 64 + c * 8 + 2 * lq;
                float v0 = acc[r][c][half * 2] * s_ + sh;
                float v1 = acc[r][c][half * 2 + 1] * s_ + sh;
                v0 = v0 / (1.f + __expf(-v0));
                v1 = v1 / (1.f + __expf(-v1));
                *(float2*)(C + (size_t)row * 4096 + col) = make_float2(v0, v1);
            }
        }
    }
}

// ---------------- attention: fp32 in, fp16 out ----------------
__global__ void attn_kernel(const float* __restrict__ qkv, __half* __restrict__ att) {
    int bp = blockIdx.x;
    int h  = blockIdx.y;
    int n  = threadIdx.x;
    __shared__ float ks[256 * 8];
    __shared__ float vs[256 * 8];
    int row = bp * 256 + n;
    const float* base = qkv + (size_t)row * 128 + h * 8;
    float4 q0 = *(const float4*)(base);
    float4 q1 = *(const float4*)(base + 4);
    *(float4*)&ks[n * 8]     = *(const float4*)(base + 32);
    *(float4*)&ks[n * 8 + 4] = *(const float4*)(base + 36);
    *(float4*)&vs[n * 8]     = *(const float4*)(base + 64);
    *(float4*)&vs[n * 8 + 4] = *(const float4*)(base + 68);
    __syncthreads();
    float q[8] = {q0.x, q0.y, q0.z, q0.w, q1.x, q1.y, q1.z, q1.w};
    #pragma unroll
    for (int j = 0; j < 8; j++) q[j] *= 0.35355339059327373f;
    float ssum = 0.f;
    float acc[8] = {};
    for (int m = 0; m < 256; m++) {
        float4 ka = *(const float4*)&ks[m * 8];
        float4 kb = *(const float4*)&ks[m * 8 + 4];
        float d = q[0]*ka.x + q[1]*ka.y + q[2]*ka.z + q[3]*ka.w
                + q[4]*kb.x + q[5]*kb.y + q[6]*kb.z + q[7]*kb.w;
        float w = __expf(d);
        ssum += w;
        float4 va = *(const float4*)&vs[m * 8];
        float4 vb = *(const float4*)&vs[m * 8 + 4];
        acc[0] += w * va.x; acc[1] += w * va.y; acc[2] += w * va.z; acc[3] += w * va.w;
        acc[4] += w * vb.x; acc[5] += w * vb.y; acc[6] += w * vb.z; acc[7] += w * vb.w;
    }
    float inv = 1.f / ssum;
    __half2 hp[4];
    #pragma unroll
    for (int j = 0; j < 4; j++)
        hp[j] = __floats2half2_rn(acc[2*j] * inv, acc[2*j+1] * inv);
    *(uint4*)(att + (size_t)row * 32 + h * 8) = *(uint4*)hp;
}

// ---------------- FFT stage 1: rfft along W ----------------
__global__ void fft1_kernel(const float* __restrict__ zp, float2* __restrict__ f1) {
    __shared__ float sX[64][128];
    __shared__ float2 tw[64];
    int c0 = blockIdx.x * 128;
    int h = blockIdx.y, b = blockIdx.z;
    int tid = threadIdx.x;
    if (tid < 64) {
        float sn, cs; sincosf(tid * PI_OVER_32, &sn, &cs);
        tw[tid] = make_float2(cs, sn);
    }
    const float* src = zp + ((size_t)(b * 64 + h) * 64) * 256 + c0;
    #pragma unroll
    for (int i = 0; i < 8; i++) {
        int idx = tid + i * 256;
        int x = idx >> 5, cc = (idx & 31) * 4;
        *(float4*)&sX[x][cc] = *(const float4*)(src + (size_t)x * 256 + cc);
    }
    __syncthreads();
    int c = tid & 127, wg = tid >> 7;
    int nw = 17 - wg;
    float re[17], im[17];
    #pragma unroll
    for (int j = 0; j < 17; j++) { re[j] = 0.f; im[j] = 0.f; }
    for (int x = 0; x < 64; x++) {
        float g = sX[x][c];
        int m = (wg * x) & 63;
        int step = (2 * x) & 63;
        #pragma unroll
        for (int j = 0; j < 17; j++) {
            if (j < nw) {
                float2 t = tw[m];
                re[j] += g * t.x;
                im[j] -= g * t.y;
                m = (m + step) & 63;
            }
        }
    }
    float2* dst = f1 + ((size_t)(b * 64 + h) * 33) * 256 + c0 + c;
    #pragma unroll
    for (int j = 0; j < 17; j++) {
        if (j < nw) {
            int w = wg + 2 * j;
            dst[(size_t)w * 256] = make_float2(re[j] * 0.125f, im[j] * 0.125f);
        }
    }
}

// ---------------- FFT stages 2+3 fused ----------------
__global__ void fft23_kernel(const float2* __restrict__ f1, const float2* __restrict__ fw,
                             float2* __restrict__ out) {
    __shared__ float2 sA[64][32];
    __shared__ float2 sB[64][32];
    __shared__ float2 tw[64];
    int w = blockIdx.x;
    int c0 = blockIdx.y * 32;
    int b = blockIdx.z;
    int tid = threadIdx.x;
    if (tid < 64) {
        float sn, cs; sincosf(tid * PI_OVER_32, &sn, &cs);
        tw[tid] = make_float2(cs, sn);
    }
    #pragma unroll
    for (int i = 0; i < 8; i++) {
        int idx = tid + i * 256;
        int hh = idx >> 5, cc = idx & 31;
        sA[hh][cc] = f1[((size_t)(b * 64 + hh) * 33 + w) * 256 + c0 + cc];
    }
    __syncthreads();

    int c = tid & 31;
    int kb = tid >> 5;
    {
        float re[8] = {}, im[8] = {};
        for (int hh = 0; hh < 64; hh++) {
            float2 g = sA[hh][c];
            int m = ((kb * 8) * hh) & 63;
            #pragma unroll
            for (int j = 0; j < 8; j++) {
                float2 t = tw[m];
                re[j] += g.x * t.x + g.y * t.y;
                im[j] += g.y * t.x - g.x * t.y;
                m = (m + hh) & 63;
            }
        }
        #pragma unroll
        for (int j = 0; j < 8; j++) {
            int k = kb * 8 + j;
            float2 wc = fw[((size_t)k * 33 + w) * 256 + c0 + c];
            float rr = re[j] * 0.125f, ii = im[j] * 0.125f;
            sB[k][c] = make_float2(rr * wc.x - ii * wc.y, rr * wc.y + ii * wc.x);
        }
    }
    __syncthreads();

    int hb = tid >> 5;
    {
        float re[8] = {}, im[8] = {};
        for (int k = 0; k < 64; k++) {
            float2 g = sB[k][c];
            int m = (k * (hb * 8)) & 63;
            #pragma unroll
            for (int j = 0; j < 8; j++) {
                float2 t = tw[m];
                re[j] += g.x * t.x - g.y * t.y;
                im[j] += g.x * t.y + g.y * t.x;
                m = (m + k) & 63;
            }
        }
        #pragma unroll
        for (int j = 0; j < 8; j++) {
            int hh = hb * 8 + j;
            out[((size_t)(b * 64 + hh) * 33 + w) * 256 + c0 + c] =
                make_float2(re[j] * 0.125f, im[j] * 0.125f);
        }
    }
}

// ---------------- FFT stage 4: irfft along W -> fp16 channel-major ----------------
__global__ void fft4_kernel(const float2* __restrict__ A, __half* __restrict__ zf) {
    __shared__ float2 sA[33][64];
    __shared__ float2 tw[64];
    int c0 = blockIdx.x * 64;
    int h = blockIdx.y, b = blockIdx.z;
    int tid = threadIdx.x;
    if (tid < 64) {
        float sn, cs; sincosf(tid * PI_OVER_32, &sn, &cs);
        tw[tid] = make_float2(cs, sn);
    }
    const float2* src = A + ((size_t)(b * 64 + h) * 33) * 256 + c0;
    for (int idx = tid; idx < 33 * 64; idx += 256) {
        int w = idx >> 6, cc = idx & 63;
        sA[w][cc] = src[(size_t)w * 256 + cc];
    }
    __syncthreads();
    int c = tid >> 2;
    int x0 = (tid & 3) * 16;
    float r[16];
    {
        float2 a0 = sA[0][c], a32 = sA[32][c];
        #pragma unroll
        for (int j = 0; j < 16; j++)
            r[j] = a0.x + (((x0 + j) & 1) ? -a32.x : a32.x);
    }
    for (int w = 1; w < 32; w++) {
        float2 a = sA[w][c];
        int m = (w * x0) & 63;
        #pragma unroll
        for (int j = 0; j < 16; j++) {
            float2 t = tw[m];
            r[j] += 2.f * (a.x * t.x - a.y * t.y);
            m = (m + w) & 63;
        }
    }
    __half2 hv[8];
    #pragma unroll
    for (int q = 0; q < 8; q++)
        hv[q] = __floats2half2_rn(r[2*q] * 0.125f, r[2*q+1] * 0.125f);
    __half* dst = zf + ((size_t)(b * 256 + c0 + c) * 64 + h) * 64 + x0;
    *(uint4*)(dst)     = *(uint4*)hv;
    *(uint4*)(dst + 8) = *(uint4*)(hv + 4);
}

// ---------------- host launch ----------------
extern "C" void kernel_launch(void* const* d_in, const int* in_sizes, int n_in,
                              void* d_out, int out_size) {
    const float* x      = (const float*)d_in[0];
    const float* ln1_g  = (const float*)d_in[1];
    const float* ln1_b  = (const float*)d_in[2];
    const float* wqkv   = (const float*)d_in[3];
    const float* wout   = (const float*)d_in[4];
    const float* bout   = (const float*)d_in[5];
    const float* ln2_g  = (const float*)d_in[6];
    const float* ln2_b  = (const float*)d_in[7];
    const float* w1     = (const float*)d_in[8];
    const float* b1     = (const float*)d_in[9];
    const float* w2     = (const float*)d_in[10];
    const float* b2     = (const float*)d_in[11];
    const float* fft_w  = (const float*)d_in[12];
    const float* conv3w = (const float*)d_in[13];
    const float* bn3_g  = (const float*)d_in[14];
    const float* bn3_b  = (const float*)d_in[15];
    const float* bn3_m  = (const float*)d_in[16];
    const float* bn3_v  = (const float*)d_in[17];
    const float* conv4w = (const float*)d_in[18];
    const float* bn4_g  = (const float*)d_in[19];
    const float* bn4_b  = (const float*)d_in[20];
    const float* bn4_m  = (const float*)d_in[21];
    const float* bn4_v  = (const float*)d_in[22];
    float* outp = (float*)d_out;

    float *u, *y, *ac, *t, *qk, *zp;
    __half *lnb, *at, *mlp, *zf, *c3;
    __half *xh, *wqkvh, *wouth, *w1h, *w2h, *c3wh, *c4wh;
    float2 *f1, *f2;
    cudaGetSymbolAddress((void**)&u,    g_u);
    cudaGetSymbolAddress((void**)&y,    g_y);
    cudaGetSymbolAddress((void**)&ac,   g_acc);
    cudaGetSymbolAddress((void**)&t,    g_t);
    cudaGetSymbolAddress((void**)&lnb,  g_ln);
    cudaGetSymbolAddress((void**)&qk,   g_qkv);
    cudaGetSymbolAddress((void**)&at,   g_att);
    cudaGetSymbolAddress((void**)&mlp,  g_mlp);
    cudaGetSymbolAddress((void**)&zp,   g_zp);
    cudaGetSymbolAddress((void**)&f1,   g_f1);
    cudaGetSymbolAddress((void**)&f2,   g_f2);
    cudaGetSymbolAddress((void**)&zf,   g_zf);
    cudaGetSymbolAddress((void**)&c3,   g_c3);
    cudaGetSymbolAddress((void**)&xh,   g_xh);
    cudaGetSymbolAddress((void**)&wqkvh,g_wqkvh);
    cudaGetSymbolAddress((void**)&wouth,g_wouth);
    cudaGetSymbolAddress((void**)&w1h,  g_w1h);
    cudaGetSymbolAddress((void**)&w2h,  g_w2h);
    cudaGetSymbolAddress((void**)&c3wh, g_c3wh);
    cudaGetSymbolAddress((void**)&c4wh, g_c4wh);

    const float* NUL = (const float*)0;
    const __half* NULH = (const __half*)0;

    // ---- one-time fp16 conversions ----
    auto f2h = [&](const float* src, __half* dst, int n) {
        int n4 = n / 4;
        f2h_kernel<<<(n4 + 255) / 256, 256>>>((const float4*)src, (uint2*)dst, n4);
    };
    f2h(x,      xh,    16 * 256 * 4096);
    f2h(wqkv,   wqkvh, 2 * 256 * 96);
    f2h(wout,   wouth, 2 * 32 * 256);
    f2h(w1,     w1h,   2 * 256 * 512);
    f2h(w2,     w2h,   2 * 512 * 256);
    f2h(conv3w, c3wh,  256 * 512);
    f2h(conv4w, c4wh,  256 * 2304);

    unfold_kernel<<<dim3(128, 8, 16), 256>>>(x, u);
    t_init_kernel<<<4096, 256>>>((const float4*)u, (float4*)t);

    for (int g = 0; g < 4; g++) {
        for (int i = 0; i < 2; i++) {
            // --- attention block ---
            ln_kernel<<<4096, 256>>>(t, ln1_g + i * 256, ln1_b + i * 256, lnb);
            gemm_kernel_t<0><<<dim3(1, 128, 1), 256>>>(lnb, wqkvh + i * 256 * 96,
                NULH, 1 << 30, qk,
                NUL, NUL, NUL, NUL, NUL, NUL,
                16384, 96, 256, 256, 96, 128, 0, 0, 0, 0);
            attn_kernel<<<dim3(64, 4), 256>>>(qk, at);
            gemm_kernel_t<0><<<dim3(2, 128, 1), 256>>>(at, wouth + i * 32 * 256,
                NULH, 1 << 30, t,
                bout + i * 256, t, NUL, NUL, NUL, NUL,
                16384, 256, 32, 32, 256, 256, 0, 0, 0, 0);
            // --- MLP block ---
            ln_kernel<<<4096, 256>>>(t, ln2_g + i * 256, ln2_b + i * 256, lnb);
            gemm_kernel_t<1><<<dim3(4, 128, 1), 256>>>(lnb, w1h + i * 256 * 512,
                NULH, 1 << 30, mlp,
                b1 + i * 512, NUL, NUL, NUL, NUL, NUL,
                16384, 512, 256, 256, 512, 512, 1, 0, 0, 0);
            gemm_kernel_t<0><<<dim3(2, 128, 1), 256>>>(mlp, w2h + i * 512 * 256,
                NULH, 1 << 30, t,
                b2 + i * 256, t, NUL, NUL, NUL, NUL,
                16384, 256, 512, 512, 256, 256, 0, 0, 0, 0);
        }
        if (g < 3)
            group_step_kernel<<<4096, 256>>>((const float4*)u, (float4*)t,
                                             (float4*)y, (float4*)ac, g, g == 0);
        else
            y_store_kernel<<<4096, 256>>>((const float4*)t, (float4*)y, 3);
    }

    fold_kernel<<<16384, 256>>>((const float4*)y, (float4*)zp);

    fft1_kernel<<<dim3(2, 64, 16), 256>>>(zp, f1);
    fft23_kernel<<<dim3(33, 8, 16), 256>>>(f1, (const float2*)fft_w, f2);
    fft4_kernel<<<dim3(4, 64, 16), 256>>>(f2, zf);

    // conv3 (1x1, 512->256): single GEMM, B = [zf ; x] dual-source (both fp16), BN+SiLU
    gemm_kernel_t<1><<<dim3(32, 2, 16), 256>>>(c3wh, zf, xh, 256, c3,
        NUL, NUL, bn3_g, bn3_b, bn3_m, bn3_v,
        256, 4096, 512, 512, 4096, 4096, 1, 0, 1048576LL, 1048576LL);

    // conv4 (3x3, 256->256) implicit GEMM (fp16 weights + image) + BN + SiLU
    conv4_gemm_kernel<<<dim3(32, 2, 16), 256>>>(c4wh, c3, outp,
                                                bn4_g, bn4_b, bn4_m, bn4_v);
}

// round 17
// speedup vs baseline: 1.1118x; 1.1118x over previous
#include <cuda_runtime.h>
#include <cuda_fp16.h>
#include <math.h>

#define EPSF 1e-5f
#define PI_OVER_32 0.09817477042468103f

// ---------------- constant permutations ----------------
__constant__ int c_IDX[16]  = {0,7,10,13,1,4,11,14,2,5,8,15,3,6,9,12};
__constant__ int c_BACK[16] = {0,4,8,12,5,9,13,1,10,14,2,6,15,3,7,11};

// ---------------- device scratch (no allocs allowed) ----------------
__device__ float  g_u  [16*16*256*256];
__device__ float  g_y  [16*16*256*256];
__device__ float  g_acc[16*4*256*256];
__device__ float  g_t  [16*4*256*256];
__device__ __half g_ln [16*4*256*256];
__device__ float  g_qkv[16*4*256*128];    // ld=128 (cols 96..127 pad)
__device__ __half g_att[16*4*256*32];
__device__ __half g_mlp[16*4*256*512];
__device__ float  g_zp [16*64*64*256];
__device__ float2 g_f1 [16*64*33*256];
__device__ float2 g_f2 [16*64*33*256];
__device__ float  g_zf [16*256*64*64];
__device__ __half g_c3 [16*256*64*64];

// fp16 m16n8k16 mma, fp32 accumulate
__device__ __forceinline__ void mma16(float* d, const unsigned* a, unsigned b0, unsigned b1) {
    asm volatile(
        "mma.sync.aligned.m16n8k16.row.col.f32.f16.f16.f32 "
        "{%0,%1,%2,%3}, {%4,%5,%6,%7}, {%8,%9}, {%0,%1,%2,%3};"
        : "+f"(d[0]), "+f"(d[1]), "+f"(d[2]), "+f"(d[3])
        : "r"(a[0]), "r"(a[1]), "r"(a[2]), "r"(a[3]), "r"(b0), "r"(b1));
}

// ---------------- tiny utility kernels ----------------
__global__ void unfold_kernel(const float* __restrict__ x, float* __restrict__ u) {
    __shared__ float tile[32][33];
    int b  = blockIdx.z;
    int c0 = blockIdx.y * 32;
    int s0 = blockIdx.x * 32;
    int tx = threadIdx.x & 31, ty = threadIdx.x >> 5;
    #pragma unroll
    for (int cc = 0; cc < 4; cc++)
        tile[ty + cc * 8][tx] =
            x[(size_t)(b * 256 + c0 + ty + cc * 8) * 4096 + s0 + tx];
    __syncthreads();
    #pragma unroll
    for (int cc = 0; cc < 4; cc++) {
        int s = s0 + ty + cc * 8;
        int h = s >> 6, w = s & 63;
        int kp = (h & 3) * 4 + (w & 3);
        int j = c_BACK[kp];
        int l = (h >> 2) * 16 + (w >> 2);
        u[((size_t)(b * 16 + j) * 256 + l) * 256 + c0 + tx] = tile[tx][ty + cc * 8];
    }
}

__device__ __forceinline__ float4 f4add(float4 a, float4 b) {
    return make_float4(a.x + b.x, a.y + b.y, a.z + b.z, a.w + b.w);
}

__global__ void t_init_kernel(const float4* __restrict__ u, float4* __restrict__ t) {
    int i = blockIdx.x * 256 + threadIdx.x;
    int c4 = i & 63;
    int l = (i >> 6) & 255;
    int p = (i >> 14) & 3;
    int b = i >> 16;
    t[i] = u[((size_t)(b * 16 + p) * 256 + l) * 64 + c4];
}

__global__ void group_step_kernel(const float4* __restrict__ u, float4* __restrict__ t,
                                  float4* __restrict__ y, float4* __restrict__ acc,
                                  int g, int first) {
    int i = blockIdx.x * 256 + threadIdx.x;
    int c4 = i & 63;
    int l = (i >> 6) & 255;
    int p = (i >> 14) & 3;
    int b = i >> 16;
    float4 v = t[i];
    y[((size_t)(b * 16 + g * 4 + p) * 256 + l) * 64 + c4] = v;
    float4 a = first ? v : f4add(acc[i], v);
    acc[i] = a;
    t[i] = f4add(u[((size_t)(b * 16 + (g + 1) * 4 + p) * 256 + l) * 64 + c4], a);
}

__global__ void y_store_kernel(const float4* __restrict__ t, float4* __restrict__ y, int g) {
    int i = blockIdx.x * 256 + threadIdx.x;
    int c4 = i & 63;
    int l = (i >> 6) & 255;
    int p = (i >> 14) & 3;
    int b = i >> 16;
    y[((size_t)(b * 16 + g * 4 + p) * 256 + l) * 64 + c4] = t[i];
}

__global__ void fold_kernel(const float4* __restrict__ y, float4* __restrict__ zp) {
    int i = blockIdx.x * 256 + threadIdx.x;
    int c4 = i & 63;
    int wp = (i >> 6) & 63;
    int hp = (i >> 12) & 63;
    int b  = i >> 18;
    int ky = hp & 3, ph = hp >> 2;
    int kx = wp & 3, pw = wp >> 2;
    int j = c_BACK[ky * 4 + kx];
    int l = ph * 16 + pw;
    zp[i] = y[((size_t)(b * 16 + j) * 256 + l) * 64 + c4];
}

// ---------------- layernorm: 4 rows per block, float4 in, fp16 out ----------------
__global__ void ln_kernel(const float* __restrict__ in, const float* __restrict__ gw,
                          const float* __restrict__ bw, __half* __restrict__ out) {
    int tid = threadIdx.x;
    int r = tid >> 6;
    int t = tid & 63;
    size_t row = (size_t)blockIdx.x * 4 + r;
    float4 v = *(const float4*)(in + row * 256 + t * 4);
    float s  = v.x + v.y + v.z + v.w;
    float sq = v.x * v.x + v.y * v.y + v.z * v.z + v.w * v.w;
    #pragma unroll
    for (int o = 16; o; o >>= 1) {
        s  += __shfl_xor_sync(0xffffffffu, s, o);
        sq += __shfl_xor_sync(0xffffffffu, sq, o);
    }
    __shared__ float ss[8], sqs[8];
    int warp = tid >> 5;
    if ((tid & 31) == 0) { ss[warp] = s; sqs[warp] = sq; }
    __syncthreads();
    s  = ss[r * 2] + ss[r * 2 + 1];
    sq = sqs[r * 2] + sqs[r * 2 + 1];
    float mean = s * (1.f / 256.f);
    float var  = sq * (1.f / 256.f) - mean * mean;
    float rstd = rsqrtf(var + EPSF);
    float4 g4 = *(const float4*)(gw + t * 4);
    float4 b4 = *(const float4*)(bw + t * 4);
    __half2 lo = __floats2half2_rn((v.x - mean) * rstd * g4.x + b4.x,
                                   (v.y - mean) * rstd * g4.y + b4.y);
    __half2 hi = __floats2half2_rn((v.z - mean) * rstd * g4.z + b4.z,
                                   (v.w - mean) * rstd * g4.w + b4.w);
    uint2 st; st.x = *(unsigned*)&lo; st.y = *(unsigned*)&hi;
    *(uint2*)(out + row * 256 + t * 4) = st;
}

// ============ fp16-mma GEMM (R12): BM=128, BN=128, BK=16, 8 warps, 32x64 warp tile ==
#define BM 128
#define BNN 128
#define BK 16
#define ALD2 10
#define BLD2 136

template<int AH, int OH>
__global__ void __launch_bounds__(256)
gemm_kernel_t(const void* __restrict__ Av, const float* __restrict__ B,
              const float* __restrict__ B2, int ksplit,
              void* __restrict__ Cv,
              const float* __restrict__ bias, const float* __restrict__ resid,
              const float* __restrict__ bnG, const float* __restrict__ bnB,
              const float* __restrict__ bnM, const float* __restrict__ bnV,
              int M, int N, int K, int lda, int ldb, int ldc,
              int act, long long sA, long long sB, long long sC) {
    __shared__ __align__(16) __half2 As2[2][BM][ALD2];
    __shared__ __align__(16) __half2 Bs2[2][8][BLD2];
    int z = blockIdx.z;
    const float*  Af = (const float*)Av  + (AH ? 0 : (size_t)z * sA);
    const __half* Ah = (const __half*)Av + (AH ? (size_t)z * sA : 0);
    B += z * sB; if (B2) B2 += z * sB;
    float*  Cf = (float*)Cv  + (OH ? 0 : (size_t)z * sC);
    __half* Ch = (__half*)Cv + (OH ? (size_t)z * sC : 0);
    const float* R = resid ? resid + (size_t)z * sC : (const float*)0;
    int bm = blockIdx.y * BM, bn = blockIdx.x * BNN;
    int tid = threadIdx.x, warp = tid >> 5, lane = tid & 31;
    int wr = warp >> 1, wc = warp & 1;
    int lg = lane >> 2, lq = lane & 3;

    float acc[2][8][4];
    #pragma unroll
    for (int r = 0; r < 2; r++)
        #pragma unroll
        for (int c = 0; c < 8; c++)
            #pragma unroll
            for (int e = 0; e < 4; e++)
                acc[r][c][e] = 0.f;

    int aRowF = tid >> 2, aColF = (tid & 3) * 4;
    int aP0 = ((aColF & 7) >> 1) * 2 + (aColF >> 3);
    int aRowH = tid >> 1, akh = (tid & 1) * 8;
    int sb = akh >> 3;
    int bRow = tid >> 5;
    int bN = (tid & 31) * 4;
    int cB = bn + bN;
    bool bOK = (cB < N);

    float4 pa[2], pb[2];
    uint4 pah;
    const float4 f4z = make_float4(0.f, 0.f, 0.f, 0.f);

    if (AH) {
        pah = *(const uint4*)(Ah + (size_t)(bm + aRowH) * lda + akh);
    } else {
        #pragma unroll
        for (int i = 0; i < 2; i++)
            pa[i] = *(const float4*)(Af + (size_t)(bm + aRowF + 64 * i) * lda + aColF);
    }
    #pragma unroll
    for (int j = 0; j < 2; j++) {
        int k = 2 * bRow + j;
        const float* q = (k < ksplit) ? B + (size_t)k * ldb
                                      : B2 + (size_t)(k - ksplit) * ldb;
        pb[j] = bOK ? *(const float4*)(q + cB) : f4z;
    }
    if (AH) {
        const __half2* hp = (const __half2*)&pah;
        #pragma unroll
        for (int p = 0; p < 4; p++)
            As2[0][aRowH][sb + 2 * p] = hp[p];
    } else {
        #pragma unroll
        for (int i = 0; i < 2; i++) {
            As2[0][aRowF + 64 * i][aP0]     = __floats2half2_rn(pa[i].x, pa[i].y);
            As2[0][aRowF + 64 * i][aP0 + 2] = __floats2half2_rn(pa[i].z, pa[i].w);
        }
    }
    {
        __half2 h[4];
        h[0] = __floats2half2_rn(pb[0].x, pb[1].x);
        h[1] = __floats2half2_rn(pb[0].y, pb[1].y);
        h[2] = __floats2half2_rn(pb[0].z, pb[1].z);
        h[3] = __floats2half2_rn(pb[0].w, pb[1].w);
        *(uint4*)&Bs2[0][bRow][bN] = *(uint4*)h;
    }
    __syncthreads();

    int cur = 0;
    for (int k0 = 0; k0 < K; k0 += BK) {
        int kn = k0 + BK;
        if (kn < K) {
            if (AH) {
                pah = *(const uint4*)(Ah + (size_t)(bm + aRowH) * lda + kn + akh);
            } else {
                #pragma unroll
                for (int i = 0; i < 2; i++)
                    pa[i] = *(const float4*)(Af + (size_t)(bm + aRowF + 64 * i) * lda + kn + aColF);
            }
            #pragma unroll
            for (int j = 0; j < 2; j++) {
                int k = kn + 2 * bRow + j;
                const float* q = (k < ksplit) ? B + (size_t)k * ldb
                                              : B2 + (size_t)(k - ksplit) * ldb;
                pb[j] = bOK ? *(const float4*)(q + cB) : f4z;
            }
        }
        {
            unsigned a[2][4];
            #pragma unroll
            for (int r = 0; r < 2; r++) {
                int row = wr * 32 + r * 16 + lg;
                uint2 lo = *(const uint2*)&As2[cur][row][2 * lq];
                uint2 hi = *(const uint2*)&As2[cur][row + 8][2 * lq];
                a[r][0] = lo.x; a[r][1] = hi.x; a[r][2] = lo.y; a[r][3] = hi.y;
            }
            #pragma unroll
            for (int c = 0; c < 8; c++) {
                int nn = wc * 64 + c * 8 + lg;
                unsigned b0 = *(const unsigned*)&Bs2[cur][lq][nn];
                unsigned b1 = *(const unsigned*)&Bs2[cur][lq + 4][nn];
                #pragma unroll
                for (int r = 0; r < 2; r++)
                    mma16(acc[r][c], a[r], b0, b1);
            }
        }
        if (kn < K) {
            if (AH) {
                const __half2* hp = (const __half2*)&pah;
                #pragma unroll
                for (int p = 0; p < 4; p++)
                    As2[cur ^ 1][aRowH][sb + 2 * p] = hp[p];
            } else {
                #pragma unroll
                for (int i = 0; i < 2; i++) {
                    As2[cur ^ 1][aRowF + 64 * i][aP0]     = __floats2half2_rn(pa[i].x, pa[i].y);
                    As2[cur ^ 1][aRowF + 64 * i][aP0 + 2] = __floats2half2_rn(pa[i].z, pa[i].w);
                }
            }
            __half2 h[4];
            h[0] = __floats2half2_rn(pb[0].x, pb[1].x);
            h[1] = __floats2half2_rn(pb[0].y, pb[1].y);
            h[2] = __floats2half2_rn(pb[0].z, pb[1].z);
            h[3] = __floats2half2_rn(pb[0].w, pb[1].w);
            *(uint4*)&Bs2[cur ^ 1][bRow][bN] = *(uint4*)h;
        }
        __syncthreads();
        cur ^= 1;
    }

    #pragma unroll
    for (int r = 0; r < 2; r++) {
        #pragma unroll
        for (int half = 0; half < 2; half++) {
            int row = bm + wr * 32 + r * 16 + lg + half * 8;
            float sc = 1.f, sh = 0.f;
            if (bnG) {
                float s_ = bnG[row] * rsqrtf(bnV[row] + EPSF);
                sc = s_; sh = bnB[row] - bnM[row] * s_;
            }
            #pragma unroll
            for (int c = 0; c < 8; c++) {
                int col = bn + wc * 64 + c * 8 + 2 * lq;
                if (col < N) {
                    float v0 = acc[r][c][half * 2];
                    float v1 = acc[r][c][half * 2 + 1];
                    if (R) {
                        float2 rv = *(const float2*)(R + (size_t)row * ldc + col);
                        v0 += rv.x; v1 += rv.y;
                    }
                    if (bias) {
                        float2 bv = *(const float2*)(bias + col);
                        v0 += bv.x; v1 += bv.y;
                    }
                    v0 = v0 * sc + sh;
                    v1 = v1 * sc + sh;
                    if (act) {
                        v0 = v0 / (1.f + __expf(-v0));
                        v1 = v1 / (1.f + __expf(-v1));
                    }
                    if (OH) {
                        __half2 hv = __floats2half2_rn(v0, v1);
                        *(__half2*)(Ch + (size_t)row * ldc + col) = hv;
                    } else {
                        *(float2*)(Cf + (size_t)row * ldc + col) = make_float2(v0, v1);
                    }
                }
            }
        }
    }
}

// ======== fused GEMM+residual+LN: BM=64, BN=256 (full rows), 8 warps (2x4) ========
// C_t = A@B + bias + resid (fp32, written); lnb = LN(C_t) (fp16, if lnOut != null)
#define BML 64
#define BNL 256
#define BLD2L 264

__global__ void __launch_bounds__(256)
gemm_ln_kernel(const __half* __restrict__ Ah, const float* __restrict__ B,
               float* __restrict__ Ct, __half* __restrict__ lnOut,
               const float* __restrict__ bias, const float* __restrict__ resid,
               const float* __restrict__ lnG, const float* __restrict__ lnB,
               int K, int lda) {
    __shared__ __align__(16) __half2 As2[2][BML][ALD2];
    __shared__ __align__(16) __half2 Bs2[2][8][BLD2L];
    __shared__ float pS[4][64], pQ[4][64];
    __shared__ float mS[64], rS[64];
    int bm = blockIdx.y * BML;
    int tid = threadIdx.x, warp = tid >> 5, lane = tid & 31;
    int wr = warp >> 2, wc = warp & 3;      // 2 row-groups x 4 col-groups
    int lg = lane >> 2, lq = lane & 3;

    float acc[2][8][4];
    #pragma unroll
    for (int r = 0; r < 2; r++)
        #pragma unroll
        for (int c = 0; c < 8; c++)
            #pragma unroll
            for (int e = 0; e < 4; e++)
                acc[r][c][e] = 0.f;

    // A: 64 rows, 4 threads/row, 4 halves each
    int aRow = tid >> 2, akh = (tid & 3) * 4;
    int q0 = (tid & 3) * 2;                 // first logical k-pair
    int slot0 = 2 * (q0 & 3) + (q0 >> 2);
    int slot1 = 2 * ((q0 + 1) & 3) + ((q0 + 1) >> 2);
    // B: fp32, 8 kpair rows, thread covers 1 kpair row x 8 cols
    int bRow = tid >> 5;
    int bN = (tid & 31) * 8;

    uint2 pahv;
    float4 pb0a, pb0b, pb1a, pb1b;

    auto loadA = [&](int k0) {
        pahv = *(const uint2*)(Ah + (size_t)(bm + aRow) * lda + k0 + akh);
    };
    auto storeA = [&](int st) {
        const __half2* hp = (const __half2*)&pahv;
        As2[st][aRow][slot0] = hp[0];
        As2[st][aRow][slot1] = hp[1];
    };
    auto loadB = [&](int k0) {
        const float* r0 = B + (size_t)(k0 + 2 * bRow) * 256 + bN;
        const float* r1 = r0 + 256;
        pb0a = *(const float4*)(r0);
        pb0b = *(const float4*)(r0 + 4);
        pb1a = *(const float4*)(r1);
        pb1b = *(const float4*)(r1 + 4);
    };
    auto storeB = [&](int st) {
        __half2 h[8];
        h[0] = __floats2half2_rn(pb0a.x, pb1a.x);
        h[1] = __floats2half2_rn(pb0a.y, pb1a.y);
        h[2] = __floats2half2_rn(pb0a.z, pb1a.z);
        h[3] = __floats2half2_rn(pb0a.w, pb1a.w);
        h[4] = __floats2half2_rn(pb0b.x, pb1b.x);
        h[5] = __floats2half2_rn(pb0b.y, pb1b.y);
        h[6] = __floats2half2_rn(pb0b.z, pb1b.z);
        h[7] = __floats2half2_rn(pb0b.w, pb1b.w);
        *(uint4*)&Bs2[st][bRow][bN]     = *(uint4*)h;
        *(uint4*)&Bs2[st][bRow][bN + 4] = *(uint4*)(h + 4);
    };

    loadA(0); loadB(0);
    storeA(0); storeB(0);
    __syncthreads();

    int cur = 0;
    for (int k0 = 0; k0 < K; k0 += BK) {
        int kn = k0 + BK;
        if (kn < K) { loadA(kn); loadB(kn); }
        {
            unsigned a[2][4];
            #pragma unroll
            for (int r = 0; r < 2; r++) {
                int row = wr * 32 + r * 16 + lg;
                uint2 lo = *(const uint2*)&As2[cur][row][2 * lq];
                uint2 hi = *(const uint2*)&As2[cur][row + 8][2 * lq];
                a[r][0] = lo.x; a[r][1] = hi.x; a[r][2] = lo.y; a[r][3] = hi.y;
            }
            #pragma unroll
            for (int c = 0; c < 8; c++) {
                int nn = wc * 64 + c * 8 + lg;
                unsigned b0 = *(const unsigned*)&Bs2[cur][lq][nn];
                unsigned b1 = *(const unsigned*)&Bs2[cur][lq + 4][nn];
                #pragma unroll
                for (int r = 0; r < 2; r++)
                    mma16(acc[r][c], a[r], b0, b1);
            }
        }
        if (kn < K) { storeA(cur ^ 1); storeB(cur ^ 1); }
        __syncthreads();
        cur ^= 1;
    }

    // phase 1: finish C_t = acc + resid + bias; write t; accumulate row sums
    float s[4] = {0.f, 0.f, 0.f, 0.f}, qq[4] = {0.f, 0.f, 0.f, 0.f};
    #pragma unroll
    for (int r = 0; r < 2; r++) {
        #pragma unroll
        for (int half = 0; half < 2; half++) {
            int rowl = wr * 32 + r * 16 + half * 8 + lg;
            size_t row = (size_t)(bm + rowl);
            int idx = r * 2 + half;
            #pragma unroll
            for (int c = 0; c < 8; c++) {
                int col = wc * 64 + c * 8 + 2 * lq;
                float v0 = acc[r][c][half * 2];
                float v1 = acc[r][c][half * 2 + 1];
                float2 rv = *(const float2*)(resid + row * 256 + col);
                float2 bv = *(const float2*)(bias + col);
                v0 += rv.x + bv.x;
                v1 += rv.y + bv.y;
                *(float2*)(Ct + row * 256 + col) = make_float2(v0, v1);
                acc[r][c][half * 2]     = v0;
                acc[r][c][half * 2 + 1] = v1;
                s[idx]  += v0 + v1;
                qq[idx] += v0 * v0 + v1 * v1;
            }
        }
    }
    if (lnOut) {
        #pragma unroll
        for (int o = 1; o <= 2; o <<= 1) {
            #pragma unroll
            for (int idx = 0; idx < 4; idx++) {
                s[idx]  += __shfl_xor_sync(0xffffffffu, s[idx], o);
                qq[idx] += __shfl_xor_sync(0xffffffffu, qq[idx], o);
            }
        }
        if (lq == 0) {
            #pragma unroll
            for (int idx = 0; idx < 4; idx++) {
                int rowl = wr * 32 + (idx >> 1) * 16 + (idx & 1) * 8 + lg;
                pS[wc][rowl] = s[idx];
                pQ[wc][rowl] = qq[idx];
            }
        }
        __syncthreads();
        if (tid < 64) {
            float S = pS[0][tid] + pS[1][tid] + pS[2][tid] + pS[3][tid];
            float Q = pQ[0][tid] + pQ[1][tid] + pQ[2][tid] + pQ[3][tid];
            float mean = S * (1.f / 256.f);
            float var  = Q * (1.f / 256.f) - mean * mean;
            mS[tid] = mean;
            rS[tid] = rsqrtf(var + EPSF);
        }
        __syncthreads();
        #pragma unroll
        for (int r = 0; r < 2; r++) {
            #pragma unroll
            for (int half = 0; half < 2; half++) {
                int rowl = wr * 32 + r * 16 + half * 8 + lg;
                size_t row = (size_t)(bm + rowl);
                float mean = mS[rowl], rstd = rS[rowl];
                #pragma unroll
                for (int c = 0; c < 8; c++) {
                    int col = wc * 64 + c * 8 + 2 * lq;
                    float2 g2 = *(const float2*)(lnG + col);
                    float2 b2 = *(const float2*)(lnB + col);
                    float v0 = acc[r][c][half * 2];
                    float v1 = acc[r][c][half * 2 + 1];
                    __half2 hv = __floats2half2_rn((v0 - mean) * rstd * g2.x + b2.x,
                                                   (v1 - mean) * rstd * g2.y + b2.y);
                    *(__half2*)(lnOut + row * 256 + col) = hv;
                }
            }
        }
    }
}

// ---------------- conv4 implicit GEMM: 8 warps, fp16 image (R12) ----------------
__global__ void __launch_bounds__(256)
conv4_gemm_kernel(const float* __restrict__ W, const __half* __restrict__ img,
                  float* __restrict__ C,
                  const float* __restrict__ bnG, const float* __restrict__ bnB,
                  const float* __restrict__ bnM, const float* __restrict__ bnV) {
    __shared__ __align__(16) __half2 As2[2][BM][ALD2];
    __shared__ __align__(16) __half2 Bs2[2][8][BLD2];
    const int K = 2304;
    int z = blockIdx.z;
    img += (size_t)z * 256 * 4096;
    C   += (size_t)z * 256 * 4096;
    int bm = blockIdx.y * BM, bn = blockIdx.x * BNN;
    int tid = threadIdx.x, warp = tid >> 5, lane = tid & 31;
    int wr = warp >> 1, wc = warp & 1;
    int lg = lane >> 2, lq = lane & 3;
    const __half hz = __float2half(0.f);

    float acc[2][8][4];
    #pragma unroll
    for (int r = 0; r < 2; r++)
        #pragma unroll
        for (int c = 0; c < 8; c++)
            #pragma unroll
            for (int e = 0; e < 4; e++)
                acc[r][c][e] = 0.f;

    int aRowF = tid >> 2, aColF = (tid & 3) * 4;
    int aP0 = ((aColF & 7) >> 1) * 2 + (aColF >> 3);
    int bRow = tid >> 5;
    int bN = (tid & 31) * 4;
    int n = bn + bN;
    int y0 = n >> 6, x0 = n & 63;

    float4 pa[2];
    __half pbv[2][4];

    auto loadB = [&](int kbase) {
        #pragma unroll
        for (int j = 0; j < 2; j++) {
            int k = kbase + 2 * bRow + j;
            int ic = k / 9, kk = k - ic * 9;
            int ky = kk / 3, kx = kk - ky * 3;
            int gy = y0 + ky - 1;
            const __half* p = img + ((size_t)ic * 64 + gy) * 64;
            bool rok = (unsigned)gy < 64u;
            #pragma unroll
            for (int e = 0; e < 4; e++) {
                int gx = x0 + e + kx - 1;
                pbv[j][e] = (rok && (unsigned)gx < 64u) ? p[gx] : hz;
            }
        }
    };
    auto storeB = [&](int st) {
        __half2 h[4];
        #pragma unroll
        for (int e = 0; e < 4; e++)
            h[e] = __halves2half2(pbv[0][e], pbv[1][e]);
        *(uint4*)&Bs2[st][bRow][bN] = *(uint4*)h;
    };

    #pragma unroll
    for (int i = 0; i < 2; i++)
        pa[i] = *(const float4*)(W + (size_t)(bm + aRowF + 64 * i) * 2304 + aColF);
    loadB(0);
    #pragma unroll
    for (int i = 0; i < 2; i++) {
        As2[0][aRowF + 64 * i][aP0]     = __floats2half2_rn(pa[i].x, pa[i].y);
        As2[0][aRowF + 64 * i][aP0 + 2] = __floats2half2_rn(pa[i].z, pa[i].w);
    }
    storeB(0);
    __syncthreads();

    int cur = 0;
    for (int k0 = 0; k0 < K; k0 += BK) {
        int kn = k0 + BK;
        if (kn < K) {
            #pragma unroll
            for (int i = 0; i < 2; i++)
                pa[i] = *(const float4*)(W + (size_t)(bm + aRowF + 64 * i) * 2304 + kn + aColF);
            loadB(kn);
        }
        {
            unsigned a[2][4];
            #pragma unroll
            for (int r = 0; r < 2; r++) {
                int row = wr * 32 + r * 16 + lg;
                uint2 lo = *(const uint2*)&As2[cur][row][2 * lq];
                uint2 hi = *(const uint2*)&As2[cur][row + 8][2 * lq];
                a[r][0] = lo.x; a[r][1] = hi.x; a[r][2] = lo.y; a[r][3] = hi.y;
            }
            #pragma unroll
            for (int c = 0; c < 8; c++) {
                int nn = wc * 64 + c * 8 + lg;
                unsigned b0 = *(const unsigned*)&Bs2[cur][lq][nn];
                unsigned b1 = *(const unsigned*)&Bs2[cur][lq + 4][nn];
                #pragma unroll
                for (int r = 0; r < 2; r++)
                    mma16(acc[r][c], a[r], b0, b1);
            }
        }
        if (kn < K) {
            #pragma unroll
            for (int i = 0; i < 2; i++) {
                As2[cur ^ 1][aRowF + 64 * i][aP0]     = __floats2half2_rn(pa[i].x, pa[i].y);
                As2[cur ^ 1][aRowF + 64 * i][aP0 + 2] = __floats2half2_rn(pa[i].z, pa[i].w);
            }
            storeB(cur ^ 1);
        }
        __syncthreads();
        cur ^= 1;
    }

    #pragma unroll
    for (int r = 0; r < 2; r++) {
        #pragma unroll
        for (int half = 0; half < 2; half++) {
            int row = bm + wr * 32 + r * 16 + lg + half * 8;
            float s_ = bnG[row] * rsqrtf(bnV[row] + EPSF);
            float sh = bnB[row] - bnM[row] * s_;
            #pragma unroll
            for (int c = 0; c < 8; c++) {
                int col = bn + wc * 64 + c * 8 + 2 * lq;
                float v0 = acc[r][c][half * 2] * s_ + sh;
                float v1 = acc[r][c][half * 2 + 1] * s_ + sh;
                v0 = v0 / (1.f + __expf(-v0));
                v1 = v1 / (1.f + __expf(-v1));
                *(float2*)(C + (size_t)row * 4096 + col) = make_float2(v0, v1);
            }
        }
    }
}

// ---------------- attention: fp32 in, fp16 out ----------------
__global__ void attn_kernel(const float* __restrict__ qkv, __half* __restrict__ att) {
    int bp = blockIdx.x;
    int h  = blockIdx.y;
    int n  = threadIdx.x;
    __shared__ float ks[256 * 8];
    __shared__ float vs[256 * 8];
    int row = bp * 256 + n;
    const float* base = qkv + (size_t)row * 128 + h * 8;
    float4 q0 = *(const float4*)(base);
    float4 q1 = *(const float4*)(base + 4);
    *(float4*)&ks[n * 8]     = *(const float4*)(base + 32);
    *(float4*)&ks[n * 8 + 4] = *(const float4*)(base + 36);
    *(float4*)&vs[n * 8]     = *(const float4*)(base + 64);
    *(float4*)&vs[n * 8 + 4] = *(const float4*)(base + 68);
    __syncthreads();
    float q[8] = {q0.x, q0.y, q0.z, q0.w, q1.x, q1.y, q1.z, q1.w};
    #pragma unroll
    for (int j = 0; j < 8; j++) q[j] *= 0.35355339059327373f;
    float ssum = 0.f;
    float acc[8] = {};
    for (int m = 0; m < 256; m++) {
        float4 ka = *(const float4*)&ks[m * 8];
        float4 kb = *(const float4*)&ks[m * 8 + 4];
        float d = q[0]*ka.x + q[1]*ka.y + q[2]*ka.z + q[3]*ka.w
                + q[4]*kb.x + q[5]*kb.y + q[6]*kb.z + q[7]*kb.w;
        float w = __expf(d);
        ssum += w;
        float4 va = *(const float4*)&vs[m * 8];
        float4 vb = *(const float4*)&vs[m * 8 + 4];
        acc[0] += w * va.x; acc[1] += w * va.y; acc[2] += w * va.z; acc[3] += w * va.w;
        acc[4] += w * vb.x; acc[5] += w * vb.y; acc[6] += w * vb.z; acc[7] += w * vb.w;
    }
    float inv = 1.f / ssum;
    __half2 hp[4];
    #pragma unroll
    for (int j = 0; j < 4; j++)
        hp[j] = __floats2half2_rn(acc[2*j] * inv, acc[2*j+1] * inv);
    *(uint4*)(att + (size_t)row * 32 + h * 8) = *(uint4*)hp;
}

// ---------------- FFT stage 1: rfft along W ----------------
__global__ void fft1_kernel(const float* __restrict__ zp, float2* __restrict__ f1) {
    __shared__ float sX[64][128];
    __shared__ float2 tw[64];
    int c0 = blockIdx.x * 128;
    int h = blockIdx.y, b = blockIdx.z;
    int tid = threadIdx.x;
    if (tid < 64) {
        float sn, cs; sincosf(tid * PI_OVER_32, &sn, &cs);
        tw[tid] = make_float2(cs, sn);
    }
    const float* src = zp + ((size_t)(b * 64 + h) * 64) * 256 + c0;
    #pragma unroll
    for (int i = 0; i < 8; i++) {
        int idx = tid + i * 256;
        int x = idx >> 5, cc = (idx & 31) * 4;
        *(float4*)&sX[x][cc] = *(const float4*)(src + (size_t)x * 256 + cc);
    }
    __syncthreads();
    int c = tid & 127, wg = tid >> 7;
    int nw = 17 - wg;
    float re[17], im[17];
    #pragma unroll
    for (int j = 0; j < 17; j++) { re[j] = 0.f; im[j] = 0.f; }
    for (int x = 0; x < 64; x++) {
        float g = sX[x][c];
        int m = (wg * x) & 63;
        int step = (2 * x) & 63;
        #pragma unroll
        for (int j = 0; j < 17; j++) {
            if (j < nw) {
                float2 t = tw[m];
                re[j] += g * t.x;
                im[j] -= g * t.y;
                m = (m + step) & 63;
            }
        }
    }
    float2* dst = f1 + ((size_t)(b * 64 + h) * 33) * 256 + c0 + c;
    #pragma unroll
    for (int j = 0; j < 17; j++) {
        if (j < nw) {
            int w = wg + 2 * j;
            dst[(size_t)w * 256] = make_float2(re[j] * 0.125f, im[j] * 0.125f);
        }
    }
}

// ---------------- FFT stages 2+3 fused ----------------
__global__ void fft23_kernel(const float2* __restrict__ f1, const float2* __restrict__ fw,
                             float2* __restrict__ out) {
    __shared__ float2 sA[64][32];
    __shared__ float2 sB[64][32];
    __shared__ float2 tw[64];
    int w = blockIdx.x;
    int c0 = blockIdx.y * 32;
    int b = blockIdx.z;
    int tid = threadIdx.x;
    if (tid < 64) {
        float sn, cs; sincosf(tid * PI_OVER_32, &sn, &cs);
        tw[tid] = make_float2(cs, sn);
    }
    #pragma unroll
    for (int i = 0; i < 8; i++) {
        int idx = tid + i * 256;
        int hh = idx >> 5, cc = idx & 31;
        sA[hh][cc] = f1[((size_t)(b * 64 + hh) * 33 + w) * 256 + c0 + cc];
    }
    __syncthreads();

    int c = tid & 31;
    int kb = tid >> 5;
    {
        float re[8] = {}, im[8] = {};
        for (int hh = 0; hh < 64; hh++) {
            float2 g = sA[hh][c];
            int m = ((kb * 8) * hh) & 63;
            #pragma unroll
            for (int j = 0; j < 8; j++) {
                float2 t = tw[m];
                re[j] += g.x * t.x + g.y * t.y;
                im[j] += g.y * t.x - g.x * t.y;
                m = (m + hh) & 63;
            }
        }
        #pragma unroll
        for (int j = 0; j < 8; j++) {
            int k = kb * 8 + j;
            float2 wc = fw[((size_t)k * 33 + w) * 256 + c0 + c];
            float rr = re[j] * 0.125f, ii = im[j] * 0.125f;
            sB[k][c] = make_float2(rr * wc.x - ii * wc.y, rr * wc.y + ii * wc.x);
        }
    }
    __syncthreads();

    int hb = tid >> 5;
    {
        float re[8] = {}, im[8] = {};
        for (int k = 0; k < 64; k++) {
            float2 g = sB[k][c];
            int m = (k * (hb * 8)) & 63;
            #pragma unroll
            for (int j = 0; j < 8; j++) {
                float2 t = tw[m];
                re[j] += g.x * t.x - g.y * t.y;
                im[j] += g.x * t.y + g.y * t.x;
                m = (m + k) & 63;
            }
        }
        #pragma unroll
        for (int j = 0; j < 8; j++) {
            int hh = hb * 8 + j;
            out[((size_t)(b * 64 + hh) * 33 + w) * 256 + c0 + c] =
                make_float2(re[j] * 0.125f, im[j] * 0.125f);
        }
    }
}

// ---------------- FFT stage 4: irfft along W ----------------
__global__ void fft4_kernel(const float2* __restrict__ A, float* __restrict__ zf) {
    __shared__ float2 sA[33][64];
    __shared__ float2 tw[64];
    int c0 = blockIdx.x * 64;
    int h = blockIdx.y, b = blockIdx.z;
    int tid = threadIdx.x;
    if (tid < 64) {
        float sn, cs; sincosf(tid * PI_OVER_32, &sn, &cs);
        tw[tid] = make_float2(cs, sn);
    }
    const float2* src = A + ((size_t)(b * 64 + h) * 33) * 256 + c0;
    for (int idx = tid; idx < 33 * 64; idx += 256) {
        int w = idx >> 6, cc = idx & 63;
        sA[w][cc] = src[(size_t)w * 256 + cc];
    }
    __syncthreads();
    int c = tid >> 2;
    int x0 = (tid & 3) * 16;
    float r[16];
    {
        float2 a0 = sA[0][c], a32 = sA[32][c];
        #pragma unroll
        for (int j = 0; j < 16; j++)
            r[j] = a0.x + (((x0 + j) & 1) ? -a32.x : a32.x);
    }
    for (int w = 1; w < 32; w++) {
        float2 a = sA[w][c];
        int m = (w * x0) & 63;
        #pragma unroll
        for (int j = 0; j < 16; j++) {
            float2 t = tw[m];
            r[j] += 2.f * (a.x * t.x - a.y * t.y);
            m = (m + w) & 63;
        }
    }
    float* dst = zf + ((size_t)(b * 256 + c0 + c) * 64 + h) * 64 + x0;
    #pragma unroll
    for (int q = 0; q < 4; q++) {
        float4 v = make_float4(r[q*4] * 0.125f, r[q*4+1] * 0.125f,
                               r[q*4+2] * 0.125f, r[q*4+3] * 0.125f);
        *(float4*)(dst + q * 4) = v;
    }
}

// ---------------- host launch ----------------
extern "C" void kernel_launch(void* const* d_in, const int* in_sizes, int n_in,
                              void* d_out, int out_size) {
    const float* x      = (const float*)d_in[0];
    const float* ln1_g  = (const float*)d_in[1];
    const float* ln1_b  = (const float*)d_in[2];
    const float* wqkv   = (const float*)d_in[3];
    const float* wout   = (const float*)d_in[4];
    const float* bout   = (const float*)d_in[5];
    const float* ln2_g  = (const float*)d_in[6];
    const float* ln2_b  = (const float*)d_in[7];
    const float* w1     = (const float*)d_in[8];
    const float* b1     = (const float*)d_in[9];
    const float* w2     = (const float*)d_in[10];
    const float* b2     = (const float*)d_in[11];
    const float* fft_w  = (const float*)d_in[12];
    const float* conv3w = (const float*)d_in[13];
    const float* bn3_g  = (const float*)d_in[14];
    const float* bn3_b  = (const float*)d_in[15];
    const float* bn3_m  = (const float*)d_in[16];
    const float* bn3_v  = (const float*)d_in[17];
    const float* conv4w = (const float*)d_in[18];
    const float* bn4_g  = (const float*)d_in[19];
    const float* bn4_b  = (const float*)d_in[20];
    const float* bn4_m  = (const float*)d_in[21];
    const float* bn4_v  = (const float*)d_in[22];
    float* outp = (float*)d_out;

    float *u, *y, *ac, *t, *qk, *zp, *zf;
    __half *lnb, *at, *mlp, *c3;
    float2 *f1, *f2;
    cudaGetSymbolAddress((void**)&u,   g_u);
    cudaGetSymbolAddress((void**)&y,   g_y);
    cudaGetSymbolAddress((void**)&ac,  g_acc);
    cudaGetSymbolAddress((void**)&t,   g_t);
    cudaGetSymbolAddress((void**)&lnb, g_ln);
    cudaGetSymbolAddress((void**)&qk,  g_qkv);
    cudaGetSymbolAddress((void**)&at,  g_att);
    cudaGetSymbolAddress((void**)&mlp, g_mlp);
    cudaGetSymbolAddress((void**)&zp,  g_zp);
    cudaGetSymbolAddress((void**)&f1,  g_f1);
    cudaGetSymbolAddress((void**)&f2,  g_f2);
    cudaGetSymbolAddress((void**)&zf,  g_zf);
    cudaGetSymbolAddress((void**)&c3,  g_c3);

    const float* NUL = (const float*)0;
    __half* NULH = (__half*)0;

    unfold_kernel<<<dim3(128, 8, 16), 256>>>(x, u);
    t_init_kernel<<<4096, 256>>>((const float4*)u, (float4*)t);

    for (int g = 0; g < 4; g++) {
        for (int i = 0; i < 2; i++) {
            // ln1: standalone only for i==0 (i==1's lnb comes from fused mlp2)
            if (i == 0)
                ln_kernel<<<4096, 256>>>(t, ln1_g, ln1_b, lnb);
            // --- attention block ---
            gemm_kernel_t<1, 0><<<dim3(1, 128, 1), 256>>>(lnb, wqkv + i * 256 * 96,
                wqkv + i * 256 * 96, 1 << 30, qk,
                NUL, NUL, NUL, NUL, NUL, NUL,
                16384, 96, 256, 256, 96, 128, 0, 0, 0, 0);
            attn_kernel<<<dim3(64, 4), 256>>>(qk, at);
            // wout + residual -> t, fused with ln2(i) -> lnb
            gemm_ln_kernel<<<dim3(1, 256, 1), 256>>>(at, wout + i * 32 * 256,
                t, lnb, bout + i * 256, t,
                ln2_g + i * 256, ln2_b + i * 256, 32, 32);
            // --- MLP block ---
            gemm_kernel_t<1, 1><<<dim3(4, 128, 1), 256>>>(lnb, w1 + i * 256 * 512,
                w1 + i * 256 * 512, 1 << 30, mlp,
                b1 + i * 512, NUL, NUL, NUL, NUL, NUL,
                16384, 512, 256, 256, 512, 512, 1, 0, 0, 0);
            // mlp2 + residual -> t; for i==0 fuse ln1(layer 1) -> lnb
            gemm_ln_kernel<<<dim3(1, 256, 1), 256>>>(mlp, w2 + i * 512 * 256,
                t, (i == 0) ? lnb : NULH, b2 + i * 256, t,
                ln1_g + 256, ln1_b + 256, 512, 512);
        }
        if (g < 3)
            group_step_kernel<<<4096, 256>>>((const float4*)u, (float4*)t,
                                             (float4*)y, (float4*)ac, g, g == 0);
        else
            y_store_kernel<<<4096, 256>>>((const float4*)t, (float4*)y, 3);
    }

    fold_kernel<<<16384, 256>>>((const float4*)y, (float4*)zp);

    fft1_kernel<<<dim3(2, 64, 16), 256>>>(zp, f1);
    fft23_kernel<<<dim3(33, 8, 16), 256>>>(f1, (const float2*)fft_w, f2);
    fft4_kernel<<<dim3(4, 64, 16), 256>>>(f2, zf);

    // conv3 (1x1, 512->256): single GEMM, B = [zf ; x] dual-source, BN+SiLU, fp16 out
    gemm_kernel_t<0, 1><<<dim3(32, 2, 16), 256>>>(conv3w, zf, x, 256, c3,
        NUL, NUL, bn3_g, bn3_b, bn3_m, bn3_v,
        256, 4096, 512, 512, 4096, 4096, 1, 0, 1048576LL, 1048576LL);

    // conv4 (3x3, 256->256) implicit GEMM (fp16 image) + BN + SiLU
    conv4_gemm_kernel<<<dim3(32, 2, 16), 256>>>(conv4w, c3, outp,
                                                bn4_g, bn4_b, bn4_m, bn4_v);
}